// round 4
// baseline (speedup 1.0000x reference)
#include <cuda_runtime.h>
#include <math.h>

// Problem constants
#define DMODEL 1024
#define DFF    4096
#define SV     196
#define QROWS  (4 * 2048)   // B*Sq = 8192

// ---------------------------------------------------------------------------
// Scratch (device globals; no allocations allowed)
// ---------------------------------------------------------------------------
__device__ float g_K1[SV * DMODEL];
__device__ float g_V1[SV * DMODEL];
__device__ float g_K2[SV * DMODEL];
__device__ float g_V2[SV * DMODEL];
__device__ float g_Q [QROWS * DMODEL];
__device__ float g_S [QROWS * SV];
__device__ float g_A [QROWS * DMODEL];
__device__ float g_O [QROWS * DMODEL];
__device__ float g_o1[QROWS * DMODEL];
__device__ float g_o2[QROWS * DMODEL];
__device__ float g_P [QROWS * DMODEL];
__device__ float g_H [QROWS * DFF];
__device__ float g_F [QROWS * DMODEL];

// ---------------------------------------------------------------------------
// Generic tiled GEMMs: BM=BN=64, BK=16, 256 threads, 4x4 per thread
// flags: 1 = add bias[n], 2 = relu, 4 = add resid[m*N+n]
// ---------------------------------------------------------------------------
#define BM 64
#define BN 64
#define BK 16

// C[M,N] = A[M,K] * B[N,K]^T  (both operands K-contiguous)
__global__ __launch_bounds__(256) void gemm_nt(
    const float* __restrict__ A, const float* __restrict__ Bm,
    const float* __restrict__ bias, const float* __restrict__ resid,
    float* __restrict__ C, int M, int N, int K, int flags)
{
    __shared__ __align__(16) float As[BK][BM + 4];
    __shared__ __align__(16) float Bs[BK][BN + 4];

    const int tid = threadIdx.x;
    const int m0 = blockIdx.y * BM;
    const int n0 = blockIdx.x * BN;
    const int ty = tid >> 4;         // 0..15
    const int tx = tid & 15;         // 0..15
    const int lr = tid >> 2;         // 0..63 (tile row)
    const int lc = (tid & 3) << 2;   // 0,4,8,12 (k offset)

    float acc[4][4];
#pragma unroll
    for (int i = 0; i < 4; i++)
#pragma unroll
        for (int j = 0; j < 4; j++) acc[i][j] = 0.f;

    for (int k0 = 0; k0 < K; k0 += BK) {
        // A tile -> As[k][m]
        {
            int row = m0 + lr;
            float4 v = make_float4(0.f, 0.f, 0.f, 0.f);
            if (row < M) {
                const float* src = A + (size_t)row * K + k0 + lc;
                if (k0 + lc + 3 < K) {
                    v = *(const float4*)src;
                } else {
                    if (k0 + lc + 0 < K) v.x = src[0];
                    if (k0 + lc + 1 < K) v.y = src[1];
                    if (k0 + lc + 2 < K) v.z = src[2];
                    if (k0 + lc + 3 < K) v.w = src[3];
                }
            }
            As[lc + 0][lr] = v.x; As[lc + 1][lr] = v.y;
            As[lc + 2][lr] = v.z; As[lc + 3][lr] = v.w;
        }
        // B tile -> Bs[k][n]
        {
            int row = n0 + lr;
            float4 v = make_float4(0.f, 0.f, 0.f, 0.f);
            if (row < N) {
                const float* src = Bm + (size_t)row * K + k0 + lc;
                if (k0 + lc + 3 < K) {
                    v = *(const float4*)src;
                } else {
                    if (k0 + lc + 0 < K) v.x = src[0];
                    if (k0 + lc + 1 < K) v.y = src[1];
                    if (k0 + lc + 2 < K) v.z = src[2];
                    if (k0 + lc + 3 < K) v.w = src[3];
                }
            }
            Bs[lc + 0][lr] = v.x; Bs[lc + 1][lr] = v.y;
            Bs[lc + 2][lr] = v.z; Bs[lc + 3][lr] = v.w;
        }
        __syncthreads();

#pragma unroll
        for (int kk = 0; kk < BK; kk++) {
            float4 a = *(const float4*)&As[kk][ty << 2];
            float4 b = *(const float4*)&Bs[kk][tx << 2];
            float av[4] = {a.x, a.y, a.z, a.w};
            float bv[4] = {b.x, b.y, b.z, b.w};
#pragma unroll
            for (int i = 0; i < 4; i++)
#pragma unroll
                for (int j = 0; j < 4; j++) acc[i][j] += av[i] * bv[j];
        }
        __syncthreads();
    }

#pragma unroll
    for (int i = 0; i < 4; i++) {
        int m = m0 + (ty << 2) + i;
        if (m >= M) continue;
#pragma unroll
        for (int j = 0; j < 4; j++) {
            int n = n0 + (tx << 2) + j;
            if (n >= N) continue;
            float v = acc[i][j];
            if (flags & 1) v += bias[n];
            if (flags & 4) v += resid[(size_t)m * N + n];
            if (flags & 2) v = fmaxf(v, 0.f);
            C[(size_t)m * N + n] = v;
        }
    }
}

// C[M,N] = A[M,K] * B[K,N]   (B row-major, N-contiguous)
__global__ __launch_bounds__(256) void gemm_nn(
    const float* __restrict__ A, const float* __restrict__ Bm,
    float* __restrict__ C, int M, int N, int K)
{
    __shared__ __align__(16) float As[BK][BM + 4];
    __shared__ __align__(16) float Bs[BK][BN + 4];

    const int tid = threadIdx.x;
    const int m0 = blockIdx.y * BM;
    const int n0 = blockIdx.x * BN;
    const int ty = tid >> 4;
    const int tx = tid & 15;
    const int lr = tid >> 2;         // 0..63
    const int lc = (tid & 3) << 2;   // 0,4,8,12
    const int kr = tid >> 4;         // 0..15 (B tile k row)
    const int nc = (tid & 15) << 2;  // 0..60 (B tile n offset)

    float acc[4][4];
#pragma unroll
    for (int i = 0; i < 4; i++)
#pragma unroll
        for (int j = 0; j < 4; j++) acc[i][j] = 0.f;

    for (int k0 = 0; k0 < K; k0 += BK) {
        // A tile -> As[k][m]
        {
            int row = m0 + lr;
            float4 v = make_float4(0.f, 0.f, 0.f, 0.f);
            if (row < M) {
                const float* src = A + (size_t)row * K + k0 + lc;
                if (k0 + lc + 3 < K) {
                    v = *(const float4*)src;
                } else {
                    if (k0 + lc + 0 < K) v.x = src[0];
                    if (k0 + lc + 1 < K) v.y = src[1];
                    if (k0 + lc + 2 < K) v.z = src[2];
                    if (k0 + lc + 3 < K) v.w = src[3];
                }
            }
            As[lc + 0][lr] = v.x; As[lc + 1][lr] = v.y;
            As[lc + 2][lr] = v.z; As[lc + 3][lr] = v.w;
        }
        // B tile -> Bs[k][n]
        {
            int krow = k0 + kr;
            float4 v = make_float4(0.f, 0.f, 0.f, 0.f);
            if (krow < K) {
                const float* src = Bm + (size_t)krow * N + n0 + nc;
                if (n0 + nc + 3 < N) {
                    v = *(const float4*)src;
                } else {
                    if (n0 + nc + 0 < N) v.x = src[0];
                    if (n0 + nc + 1 < N) v.y = src[1];
                    if (n0 + nc + 2 < N) v.z = src[2];
                    if (n0 + nc + 3 < N) v.w = src[3];
                }
            }
            Bs[kr][nc + 0] = v.x; Bs[kr][nc + 1] = v.y;
            Bs[kr][nc + 2] = v.z; Bs[kr][nc + 3] = v.w;
        }
        __syncthreads();

#pragma unroll
        for (int kk = 0; kk < BK; kk++) {
            float4 a = *(const float4*)&As[kk][ty << 2];
            float4 b = *(const float4*)&Bs[kk][tx << 2];
            float av[4] = {a.x, a.y, a.z, a.w};
            float bv[4] = {b.x, b.y, b.z, b.w};
#pragma unroll
            for (int i = 0; i < 4; i++)
#pragma unroll
                for (int j = 0; j < 4; j++) acc[i][j] += av[i] * bv[j];
        }
        __syncthreads();
    }

#pragma unroll
    for (int i = 0; i < 4; i++) {
        int m = m0 + (ty << 2) + i;
        if (m >= M) continue;
#pragma unroll
        for (int j = 0; j < 4; j++) {
            int n = n0 + (tx << 2) + j;
            if (n >= N) continue;
            C[(size_t)m * N + n] = acc[i][j];
        }
    }
}

// ---------------------------------------------------------------------------
// Softmax over Sv=196: w = softmax((S + score) / 8)
// ---------------------------------------------------------------------------
__global__ __launch_bounds__(256) void softmax_kernel(
    float* __restrict__ S, const float* __restrict__ score)
{
    const int r = blockIdx.x;
    const int t = threadIdx.x;
    __shared__ float red[256];

    float myval = 0.f;
    float v = -1e30f;
    if (t < SV) {
        myval = (S[(size_t)r * SV + t] + score[(size_t)r * SV + t]) * 0.125f;
        v = myval;
    }
    red[t] = v;
    __syncthreads();
    for (int s = 128; s > 0; s >>= 1) {
        if (t < s) red[t] = fmaxf(red[t], red[t + s]);
        __syncthreads();
    }
    const float mx = red[0];
    __syncthreads();

    float e = (t < SV) ? __expf(myval - mx) : 0.f;
    red[t] = e;
    __syncthreads();
    for (int s = 128; s > 0; s >>= 1) {
        if (t < s) red[t] += red[t + s];
        __syncthreads();
    }
    const float inv = 1.f / red[0];
    if (t < SV) S[(size_t)r * SV + t] = e * inv;
}

// ---------------------------------------------------------------------------
// LayerNorm over D=1024 (input already includes residual)
// ---------------------------------------------------------------------------
__global__ __launch_bounds__(256) void layernorm_kernel(
    const float* __restrict__ X, const float* __restrict__ g,
    const float* __restrict__ b, float* __restrict__ Y)
{
    const int r = blockIdx.x;
    const int t = threadIdx.x;
    const float* x = X + (size_t)r * DMODEL;

    float vals[4];
    float s = 0.f, ss = 0.f;
#pragma unroll
    for (int i = 0; i < 4; i++) {
        float v = x[t + i * 256];
        vals[i] = v;
        s += v;
        ss += v * v;
    }
    __shared__ float rs[256], rss[256];
    rs[t] = s; rss[t] = ss;
    __syncthreads();
    for (int k = 128; k > 0; k >>= 1) {
        if (t < k) { rs[t] += rs[t + k]; rss[t] += rss[t + k]; }
        __syncthreads();
    }
    const float mu = rs[0] * (1.f / DMODEL);
    const float var = rss[0] * (1.f / DMODEL) - mu * mu;
    const float inv = rsqrtf(var + 1e-6f);
#pragma unroll
    for (int i = 0; i < 4; i++) {
        int c = t + i * 256;
        Y[(size_t)r * DMODEL + c] = (vals[i] - mu) * inv * g[c] + b[c];
    }
}

// ---------------------------------------------------------------------------
// Concat + MaxPool1d(k=2,s=2):
// pooled[r,c] = c<512 ? max(o1[r,2c],o1[r,2c+1]) : max(o2[r,2c-1024],o2[r,2c-1023])
// ---------------------------------------------------------------------------
__global__ __launch_bounds__(256) void pool_kernel(
    const float* __restrict__ o1, const float* __restrict__ o2,
    float* __restrict__ P)
{
    size_t idx = (size_t)blockIdx.x * 256 + threadIdx.x;
    int c = (int)(idx & (DMODEL - 1));
    size_t r = idx >> 10;
    const float* src = (c < 512) ? (o1 + r * DMODEL + 2 * c)
                                 : (o2 + r * DMODEL + 2 * c - DMODEL);
    P[idx] = fmaxf(src[0], src[1]);
}

// ---------------------------------------------------------------------------
// Host orchestration
// ---------------------------------------------------------------------------
extern "C" void kernel_launch(void* const* d_in, const int* in_sizes, int n_in,
                              void* d_out, int out_size)
{
    const float* text1 = (const float*)d_in[0];
    const float* vis1  = (const float*)d_in[1];
    const float* sc1   = (const float*)d_in[2];
    const float* text2 = (const float*)d_in[3];
    const float* vis2  = (const float*)d_in[4];
    const float* sc2   = (const float*)d_in[5];
    const float* Wq = (const float*)d_in[6],  *bq = (const float*)d_in[7];
    const float* Wk = (const float*)d_in[8],  *bk = (const float*)d_in[9];
    const float* Wv = (const float*)d_in[10], *bv = (const float*)d_in[11];
    const float* Wo = (const float*)d_in[12], *bo = (const float*)d_in[13];
    const float* W1 = (const float*)d_in[14], *b1 = (const float*)d_in[15];
    const float* W2 = (const float*)d_in[16], *b2 = (const float*)d_in[17];
    const float* g1 = (const float*)d_in[18], *be1 = (const float*)d_in[19];
    const float* g2 = (const float*)d_in[20], *be2 = (const float*)d_in[21];
    float* out = (float*)d_out;

    float *K1, *V1, *K2, *V2, *Q, *S, *A, *O, *o1, *o2, *P, *H, *F;
    cudaGetSymbolAddress((void**)&K1, g_K1);
    cudaGetSymbolAddress((void**)&V1, g_V1);
    cudaGetSymbolAddress((void**)&K2, g_K2);
    cudaGetSymbolAddress((void**)&V2, g_V2);
    cudaGetSymbolAddress((void**)&Q,  g_Q);
    cudaGetSymbolAddress((void**)&S,  g_S);
    cudaGetSymbolAddress((void**)&A,  g_A);
    cudaGetSymbolAddress((void**)&O,  g_O);
    cudaGetSymbolAddress((void**)&o1, g_o1);
    cudaGetSymbolAddress((void**)&o2, g_o2);
    cudaGetSymbolAddress((void**)&P,  g_P);
    cudaGetSymbolAddress((void**)&H,  g_H);
    cudaGetSymbolAddress((void**)&F,  g_F);

    const dim3 blk(256);
    const dim3 gKV(DMODEL / BN, (SV + BM - 1) / BM);       // 16 x 4
    const dim3 gProj(DMODEL / BN, QROWS / BM);             // 16 x 128
    const dim3 gScore((SV + BN - 1) / BN, QROWS / BM);     // 4  x 128
    const dim3 gFfn1(DFF / BN, QROWS / BM);                // 64 x 128

    // K/V projections for both visual tensors
    gemm_nt<<<gKV, blk>>>(vis1, Wk, bk, nullptr, K1, SV, DMODEL, DMODEL, 1);
    gemm_nt<<<gKV, blk>>>(vis1, Wv, bv, nullptr, V1, SV, DMODEL, DMODEL, 1);
    gemm_nt<<<gKV, blk>>>(vis2, Wk, bk, nullptr, K2, SV, DMODEL, DMODEL, 1);
    gemm_nt<<<gKV, blk>>>(vis2, Wv, bv, nullptr, V2, SV, DMODEL, DMODEL, 1);

    // Branch 1
    gemm_nt<<<gProj, blk>>>(text1, Wq, bq, nullptr, Q, QROWS, DMODEL, DMODEL, 1);
    gemm_nt<<<gScore, blk>>>(Q, K1, nullptr, nullptr, S, QROWS, SV, DMODEL, 0);
    softmax_kernel<<<QROWS, blk>>>(S, sc1);
    gemm_nn<<<gProj, blk>>>(S, V1, A, QROWS, DMODEL, SV);
    gemm_nt<<<gProj, blk>>>(A, Wo, bo, text1, O, QROWS, DMODEL, DMODEL, 1 | 4);
    layernorm_kernel<<<QROWS, blk>>>(O, g1, be1, o1);

    // Branch 2
    gemm_nt<<<gProj, blk>>>(text2, Wq, bq, nullptr, Q, QROWS, DMODEL, DMODEL, 1);
    gemm_nt<<<gScore, blk>>>(Q, K2, nullptr, nullptr, S, QROWS, SV, DMODEL, 0);
    softmax_kernel<<<QROWS, blk>>>(S, sc2);
    gemm_nn<<<gProj, blk>>>(S, V2, A, QROWS, DMODEL, SV);
    gemm_nt<<<gProj, blk>>>(A, Wo, bo, text2, O, QROWS, DMODEL, DMODEL, 1 | 4);
    layernorm_kernel<<<QROWS, blk>>>(O, g1, be1, o2);

    // Concat + MaxPool
    pool_kernel<<<(QROWS * DMODEL) / 256, blk>>>(o1, o2, P);

    // FFN + residual + final LN
    gemm_nt<<<gFfn1, blk>>>(P, W1, b1, nullptr, H, QROWS, DFF, DMODEL, 1 | 2);
    gemm_nt<<<gProj, blk>>>(H, W2, b2, P, F, QROWS, DMODEL, DFF, 1 | 4);
    layernorm_kernel<<<QROWS, blk>>>(F, g2, be2, out);
}

// round 5
// speedup vs baseline: 5.3856x; 5.3856x over previous
#include <cuda_runtime.h>
#include <cuda_fp16.h>
#include <stdint.h>
#include <math.h>

#define DMODEL 1024
#define DFF    4096
#define SV     196
#define SVP    256          // padded Sv
#define QROWS  (4 * 2048)   // 8192

// ---------------------------------------------------------------------------
// Scratch (device globals; allocations forbidden)
// ---------------------------------------------------------------------------
__device__ __half g_tex1h[QROWS * DMODEL];
__device__ __half g_tex2h[QROWS * DMODEL];
__device__ __half g_vis1h[SVP * DMODEL];
__device__ __half g_vis2h[SVP * DMODEL];
__device__ __half g_Wqh[DMODEL * DMODEL];
__device__ __half g_Wkh[DMODEL * DMODEL];
__device__ __half g_Wvh[DMODEL * DMODEL];
__device__ __half g_Woh[DMODEL * DMODEL];
__device__ __half g_W1h[DFF * DMODEL];
__device__ __half g_W2h[DMODEL * DFF];
__device__ __half g_K1h[SVP * DMODEL];
__device__ __half g_K2h[SVP * DMODEL];
__device__ __half g_V1T[DMODEL * SVP];   // transposed V: [n][sv]
__device__ __half g_V2T[DMODEL * SVP];
__device__ __half g_Qh [QROWS * DMODEL];
__device__ float  g_S  [QROWS * SVP];
__device__ __half g_S16[QROWS * SVP];
__device__ __half g_Ah [QROWS * DMODEL];
__device__ float  g_O  [QROWS * DMODEL];
__device__ float  g_o1 [QROWS * DMODEL];
__device__ float  g_o2 [QROWS * DMODEL];
__device__ float  g_P  [QROWS * DMODEL];
__device__ __half g_Ph [QROWS * DMODEL];
__device__ __half g_Hh [QROWS * DFF];
__device__ float  g_F  [QROWS * DMODEL];

// ---------------------------------------------------------------------------
// f32 -> f16 conversion (vectorized by 4)
// ---------------------------------------------------------------------------
__global__ __launch_bounds__(256) void cvt4(
    const float* __restrict__ s, __half* __restrict__ d, int n4)
{
    int i = blockIdx.x * 256 + threadIdx.x;
    if (i < n4) {
        float4 v = ((const float4*)s)[i];
        __half2* dp = (__half2*)d;
        dp[2 * i + 0] = __floats2half2_rn(v.x, v.y);
        dp[2 * i + 1] = __floats2half2_rn(v.z, v.w);
    }
}

// ---------------------------------------------------------------------------
// HMMA GEMM:  C[M,N] = A[M,K] (f16, row-major) * B[N,K]^T (f16, row-major)
// BM=BN=128, BK=32, 256 threads (8 warps: 4 along M x 2 along N),
// warp tile 32x64 via mma.sync m16n8k16, cp.async double buffer.
// A rows >= Mreal are treated as zero, and output rows >= Mreal store 0.
// Epilogue: optional bias (f32, [N]), resid (f32, [M,N]), relu,
//           outputs to outF (f32), outH (f16), outHT (f16 transposed, ld=SVP).
// ---------------------------------------------------------------------------
#define BM 128
#define BN 128
#define BKH 32
#define ASTRIDE 40              // halfs per smem row (80B: conflict-free LDSM)
#define TILE_H  (BM * ASTRIDE)  // halfs per tile buffer

__device__ __forceinline__ void ldsm4(uint32_t addr,
    uint32_t& r0, uint32_t& r1, uint32_t& r2, uint32_t& r3)
{
    asm volatile("ldmatrix.sync.aligned.m8n8.x4.shared.b16 {%0,%1,%2,%3},[%4];\n"
        : "=r"(r0), "=r"(r1), "=r"(r2), "=r"(r3) : "r"(addr));
}

__device__ __forceinline__ void mma16816(float* c,
    const uint32_t* a, uint32_t b0, uint32_t b1)
{
    asm volatile(
        "mma.sync.aligned.m16n8k16.row.col.f32.f16.f16.f32 "
        "{%0,%1,%2,%3},{%4,%5,%6,%7},{%8,%9},{%0,%1,%2,%3};\n"
        : "+f"(c[0]), "+f"(c[1]), "+f"(c[2]), "+f"(c[3])
        : "r"(a[0]), "r"(a[1]), "r"(a[2]), "r"(a[3]), "r"(b0), "r"(b1));
}

__device__ __forceinline__ void cp16(uint32_t saddr, const void* gaddr, int sz)
{
    asm volatile("cp.async.cg.shared.global [%0], [%1], 16, %2;\n"
        :: "r"(saddr), "l"(gaddr), "r"(sz));
}

__global__ __launch_bounds__(256, 2) void hgemm_nt(
    const __half* __restrict__ A, const __half* __restrict__ B,
    int M, int N, int K, int Mreal,
    const float* __restrict__ bias, const float* __restrict__ resid,
    float* __restrict__ outF, __half* __restrict__ outH,
    __half* __restrict__ outHT, int relu)
{
    __shared__ __half sm[2][2][TILE_H];   // [stage][A=0/B=1][...]

    const int tid  = threadIdx.x;
    const int lane = tid & 31;
    const int wid  = tid >> 5;
    const int warp_m = wid & 3;   // *32
    const int warp_n = wid >> 2;  // *64
    const int m0 = blockIdx.y * BM;
    const int n0 = blockIdx.x * BN;

    const uint32_t smbase = (uint32_t)__cvta_generic_to_shared(&sm[0][0][0]);

    float acc[2][8][4];
#pragma unroll
    for (int i = 0; i < 2; i++)
#pragma unroll
        for (int j = 0; j < 8; j++)
#pragma unroll
            for (int r = 0; r < 4; r++) acc[i][j][r] = 0.f;

    // load chunk mapping: 512 16B chunks per tile; this thread does tid, tid+256
    const int r0c = tid >> 2,          c0c = tid & 3;
    const int r1c = (tid + 256) >> 2,  c1c = tid & 3;

    auto issue = [&](int stage, int k0) {
        // A tile
        {
            uint32_t s0 = smbase + (uint32_t)((stage * 2 + 0) * TILE_H + r0c * ASTRIDE + c0c * 8) * 2;
            uint32_t s1 = smbase + (uint32_t)((stage * 2 + 0) * TILE_H + r1c * ASTRIDE + c1c * 8) * 2;
            cp16(s0, A + (size_t)(m0 + r0c) * K + k0 + c0c * 8, (m0 + r0c) < Mreal ? 16 : 0);
            cp16(s1, A + (size_t)(m0 + r1c) * K + k0 + c1c * 8, (m0 + r1c) < Mreal ? 16 : 0);
        }
        // B tile
        {
            uint32_t s0 = smbase + (uint32_t)((stage * 2 + 1) * TILE_H + r0c * ASTRIDE + c0c * 8) * 2;
            uint32_t s1 = smbase + (uint32_t)((stage * 2 + 1) * TILE_H + r1c * ASTRIDE + c1c * 8) * 2;
            cp16(s0, B + (size_t)(n0 + r0c) * K + k0 + c0c * 8, 16);
            cp16(s1, B + (size_t)(n0 + r1c) * K + k0 + c1c * 8, 16);
        }
        asm volatile("cp.async.commit_group;\n");
    };

    const int nk = K / BKH;
    issue(0, 0);

    for (int it = 0; it < nk; it++) {
        if (it + 1 < nk) {
            issue((it + 1) & 1, (it + 1) * BKH);
            asm volatile("cp.async.wait_group 1;\n");
        } else {
            asm volatile("cp.async.wait_group 0;\n");
        }
        __syncthreads();

        const int st = it & 1;
        const uint32_t aB = smbase + (uint32_t)((st * 2 + 0) * TILE_H) * 2;
        const uint32_t bB = smbase + (uint32_t)((st * 2 + 1) * TILE_H) * 2;

#pragma unroll
        for (int kk = 0; kk < BKH; kk += 16) {
            uint32_t a[2][4];
#pragma unroll
            for (int mi = 0; mi < 2; mi++) {
                uint32_t addr = aB + (uint32_t)(
                    (warp_m * 32 + mi * 16 + (lane & 15)) * ASTRIDE +
                    kk + ((lane >> 4) << 3)) * 2;
                ldsm4(addr, a[mi][0], a[mi][1], a[mi][2], a[mi][3]);
            }
            uint32_t b[4][4];
#pragma unroll
            for (int nj = 0; nj < 4; nj++) {
                uint32_t addr = bB + (uint32_t)(
                    (warp_n * 64 + nj * 16 + (lane & 7) + ((lane >> 4) << 3)) * ASTRIDE +
                    kk + (((lane >> 3) & 1) << 3)) * 2;
                ldsm4(addr, b[nj][0], b[nj][1], b[nj][2], b[nj][3]);
            }
#pragma unroll
            for (int mi = 0; mi < 2; mi++)
#pragma unroll
                for (int nf = 0; nf < 8; nf++) {
                    const int nj = nf >> 1;
                    uint32_t b0 = (nf & 1) ? b[nj][2] : b[nj][0];
                    uint32_t b1 = (nf & 1) ? b[nj][3] : b[nj][1];
                    mma16816(acc[mi][nf], a[mi], b0, b1);
                }
        }
        __syncthreads();
    }

    // Epilogue
#pragma unroll
    for (int mi = 0; mi < 2; mi++)
#pragma unroll
        for (int nf = 0; nf < 8; nf++)
#pragma unroll
            for (int r = 0; r < 4; r++) {
                int m = m0 + warp_m * 32 + mi * 16 + (lane >> 2) + ((r >= 2) ? 8 : 0);
                int n = n0 + warp_n * 64 + nf * 8 + (lane & 3) * 2 + (r & 1);
                float v = acc[mi][nf][r];
                if (bias)  v += bias[n];
                if (resid) v += resid[(size_t)m * N + n];
                if (relu)  v = fmaxf(v, 0.f);
                if (m >= Mreal) v = 0.f;
                if (outF)  outF[(size_t)m * N + n] = v;
                if (outH)  outH[(size_t)m * N + n] = __float2half_rn(v);
                if (outHT) outHT[(size_t)n * SVP + m] = __float2half_rn(v);
            }
}

// ---------------------------------------------------------------------------
// Softmax over Sv=196: w = softmax((S + score)/8); writes f16 with zero pad
// S stride SVP(=256), score stride SV(=196)
// ---------------------------------------------------------------------------
__global__ __launch_bounds__(256) void softmax_kernel(
    const float* __restrict__ S, const float* __restrict__ score,
    __half* __restrict__ S16)
{
    const int r = blockIdx.x;
    const int t = threadIdx.x;
    __shared__ float red[256];

    float myval = 0.f;
    float v = -1e30f;
    if (t < SV) {
        myval = (S[(size_t)r * SVP + t] + score[(size_t)r * SV + t]) * 0.125f;
        v = myval;
    }
    red[t] = v;
    __syncthreads();
    for (int s = 128; s > 0; s >>= 1) {
        if (t < s) red[t] = fmaxf(red[t], red[t + s]);
        __syncthreads();
    }
    const float mx = red[0];
    __syncthreads();

    float e = (t < SV) ? __expf(myval - mx) : 0.f;
    red[t] = e;
    __syncthreads();
    for (int s = 128; s > 0; s >>= 1) {
        if (t < s) red[t] += red[t + s];
        __syncthreads();
    }
    const float inv = 1.f / red[0];
    S16[(size_t)r * SVP + t] = __float2half_rn((t < SV) ? e * inv : 0.f);
}

// ---------------------------------------------------------------------------
// LayerNorm over D=1024
// ---------------------------------------------------------------------------
__global__ __launch_bounds__(256) void layernorm_kernel(
    const float* __restrict__ X, const float* __restrict__ g,
    const float* __restrict__ b, float* __restrict__ Y)
{
    const int r = blockIdx.x;
    const int t = threadIdx.x;
    const float* x = X + (size_t)r * DMODEL;

    float vals[4];
    float s = 0.f, ss = 0.f;
#pragma unroll
    for (int i = 0; i < 4; i++) {
        float v = x[t + i * 256];
        vals[i] = v;
        s += v;
        ss += v * v;
    }
    __shared__ float rs[256], rss[256];
    rs[t] = s; rss[t] = ss;
    __syncthreads();
    for (int k = 128; k > 0; k >>= 1) {
        if (t < k) { rs[t] += rs[t + k]; rss[t] += rss[t + k]; }
        __syncthreads();
    }
    const float mu = rs[0] * (1.f / DMODEL);
    const float var = rss[0] * (1.f / DMODEL) - mu * mu;
    const float inv = rsqrtf(var + 1e-6f);
#pragma unroll
    for (int i = 0; i < 4; i++) {
        int c = t + i * 256;
        Y[(size_t)r * DMODEL + c] = (vals[i] - mu) * inv * g[c] + b[c];
    }
}

// ---------------------------------------------------------------------------
// Concat + MaxPool1d(k=2,s=2) -> P (f32) and Ph (f16)
// ---------------------------------------------------------------------------
__global__ __launch_bounds__(256) void pool_kernel(
    const float* __restrict__ o1, const float* __restrict__ o2,
    float* __restrict__ P, __half* __restrict__ Ph)
{
    size_t idx = (size_t)blockIdx.x * 256 + threadIdx.x;
    int c = (int)(idx & (DMODEL - 1));
    size_t r = idx >> 10;
    const float* src = (c < 512) ? (o1 + r * DMODEL + 2 * c)
                                 : (o2 + r * DMODEL + 2 * c - DMODEL);
    float v = fmaxf(src[0], src[1]);
    P[idx] = v;
    Ph[idx] = __float2half_rn(v);
}

// ---------------------------------------------------------------------------
// Host orchestration
// ---------------------------------------------------------------------------
extern "C" void kernel_launch(void* const* d_in, const int* in_sizes, int n_in,
                              void* d_out, int out_size)
{
    const float* text1 = (const float*)d_in[0];
    const float* vis1  = (const float*)d_in[1];
    const float* sc1   = (const float*)d_in[2];
    const float* text2 = (const float*)d_in[3];
    const float* vis2  = (const float*)d_in[4];
    const float* sc2   = (const float*)d_in[5];
    const float* Wq = (const float*)d_in[6];
    const float* Wk = (const float*)d_in[8],  *bk = (const float*)d_in[9];
    const float* bq = (const float*)d_in[7];
    const float* Wv = (const float*)d_in[10], *bv = (const float*)d_in[11];
    const float* Wo = (const float*)d_in[12], *bo = (const float*)d_in[13];
    const float* W1 = (const float*)d_in[14], *b1 = (const float*)d_in[15];
    const float* W2 = (const float*)d_in[16], *b2 = (const float*)d_in[17];
    const float* g1 = (const float*)d_in[18], *be1 = (const float*)d_in[19];
    const float* g2 = (const float*)d_in[20], *be2 = (const float*)d_in[21];
    float* out = (float*)d_out;

    __half *tex1h, *tex2h, *vis1h, *vis2h, *Wqh, *Wkh, *Wvh, *Woh, *W1h, *W2h;
    __half *K1h, *K2h, *V1T, *V2T, *Qh, *S16, *Ah, *Ph, *Hh;
    float *S, *O, *o1, *o2, *P, *F;
    cudaGetSymbolAddress((void**)&tex1h, g_tex1h);
    cudaGetSymbolAddress((void**)&tex2h, g_tex2h);
    cudaGetSymbolAddress((void**)&vis1h, g_vis1h);
    cudaGetSymbolAddress((void**)&vis2h, g_vis2h);
    cudaGetSymbolAddress((void**)&Wqh, g_Wqh);
    cudaGetSymbolAddress((void**)&Wkh, g_Wkh);
    cudaGetSymbolAddress((void**)&Wvh, g_Wvh);
    cudaGetSymbolAddress((void**)&Woh, g_Woh);
    cudaGetSymbolAddress((void**)&W1h, g_W1h);
    cudaGetSymbolAddress((void**)&W2h, g_W2h);
    cudaGetSymbolAddress((void**)&K1h, g_K1h);
    cudaGetSymbolAddress((void**)&K2h, g_K2h);
    cudaGetSymbolAddress((void**)&V1T, g_V1T);
    cudaGetSymbolAddress((void**)&V2T, g_V2T);
    cudaGetSymbolAddress((void**)&Qh,  g_Qh);
    cudaGetSymbolAddress((void**)&S,   g_S);
    cudaGetSymbolAddress((void**)&S16, g_S16);
    cudaGetSymbolAddress((void**)&Ah,  g_Ah);
    cudaGetSymbolAddress((void**)&O,   g_O);
    cudaGetSymbolAddress((void**)&o1,  g_o1);
    cudaGetSymbolAddress((void**)&o2,  g_o2);
    cudaGetSymbolAddress((void**)&P,   g_P);
    cudaGetSymbolAddress((void**)&Ph,  g_Ph);
    cudaGetSymbolAddress((void**)&Hh,  g_Hh);
    cudaGetSymbolAddress((void**)&F,   g_F);

    const dim3 blk(256);

    // ---- conversions to f16 ----
    auto cvt = [&](const float* s, __half* d, int n) {
        int n4 = n / 4;
        cvt4<<<(n4 + 255) / 256, blk>>>(s, d, n4);
    };
    cvt(text1, tex1h, QROWS * DMODEL);
    cvt(text2, tex2h, QROWS * DMODEL);
    cvt(vis1,  vis1h, SV * DMODEL);
    cvt(vis2,  vis2h, SV * DMODEL);
    cvt(Wq, Wqh, DMODEL * DMODEL);
    cvt(Wk, Wkh, DMODEL * DMODEL);
    cvt(Wv, Wvh, DMODEL * DMODEL);
    cvt(Wo, Woh, DMODEL * DMODEL);
    cvt(W1, W1h, DFF * DMODEL);
    cvt(W2, W2h, DMODEL * DFF);

    const dim3 gKV(DMODEL / BN, SVP / BM);      // 8 x 2
    const dim3 gProj(DMODEL / BN, QROWS / BM);  // 8 x 64
    const dim3 gScore(SVP / BN, QROWS / BM);    // 2 x 64
    const dim3 gFfn1(DFF / BN, QROWS / BM);     // 32 x 64

    // ---- K/V projections (M padded to 256, real 196) ----
    hgemm_nt<<<gKV, blk>>>(vis1h, Wkh, SVP, DMODEL, DMODEL, SV, bk, nullptr,
                           nullptr, K1h, nullptr, 0);
    hgemm_nt<<<gKV, blk>>>(vis1h, Wvh, SVP, DMODEL, DMODEL, SV, bv, nullptr,
                           nullptr, nullptr, V1T, 0);
    hgemm_nt<<<gKV, blk>>>(vis2h, Wkh, SVP, DMODEL, DMODEL, SV, bk, nullptr,
                           nullptr, K2h, nullptr, 0);
    hgemm_nt<<<gKV, blk>>>(vis2h, Wvh, SVP, DMODEL, DMODEL, SV, bv, nullptr,
                           nullptr, nullptr, V2T, 0);

    // ---- Branch 1 ----
    hgemm_nt<<<gProj, blk>>>(tex1h, Wqh, QROWS, DMODEL, DMODEL, QROWS, bq, nullptr,
                             nullptr, Qh, nullptr, 0);
    hgemm_nt<<<gScore, blk>>>(Qh, K1h, QROWS, SVP, DMODEL, QROWS, nullptr, nullptr,
                              S, nullptr, nullptr, 0);
    softmax_kernel<<<QROWS, blk>>>(S, sc1, S16);
    hgemm_nt<<<gProj, blk>>>(S16, V1T, QROWS, DMODEL, SVP, QROWS, nullptr, nullptr,
                             nullptr, Ah, nullptr, 0);
    hgemm_nt<<<gProj, blk>>>(Ah, Woh, QROWS, DMODEL, DMODEL, QROWS, bo, text1,
                             O, nullptr, nullptr, 0);
    layernorm_kernel<<<QROWS, blk>>>(O, g1, be1, o1);

    // ---- Branch 2 ----
    hgemm_nt<<<gProj, blk>>>(tex2h, Wqh, QROWS, DMODEL, DMODEL, QROWS, bq, nullptr,
                             nullptr, Qh, nullptr, 0);
    hgemm_nt<<<gScore, blk>>>(Qh, K2h, QROWS, SVP, DMODEL, QROWS, nullptr, nullptr,
                              S, nullptr, nullptr, 0);
    softmax_kernel<<<QROWS, blk>>>(S, sc2, S16);
    hgemm_nt<<<gProj, blk>>>(S16, V2T, QROWS, DMODEL, SVP, QROWS, nullptr, nullptr,
                             nullptr, Ah, nullptr, 0);
    hgemm_nt<<<gProj, blk>>>(Ah, Woh, QROWS, DMODEL, DMODEL, QROWS, bo, text2,
                             O, nullptr, nullptr, 0);
    layernorm_kernel<<<QROWS, blk>>>(O, g1, be1, o2);

    // ---- Concat + MaxPool ----
    pool_kernel<<<(QROWS * DMODEL) / 256, blk>>>(o1, o2, P, Ph);

    // ---- FFN + residual + final LN ----
    hgemm_nt<<<gFfn1, blk>>>(Ph, W1h, QROWS, DFF, DMODEL, QROWS, b1, nullptr,
                             nullptr, Hh, nullptr, 1);
    hgemm_nt<<<gProj, blk>>>(Hh, W2h, QROWS, DMODEL, DFF, QROWS, b2, P,
                             F, nullptr, nullptr, 0);
    layernorm_kernel<<<QROWS, blk>>>(F, g2, be2, out);
}